// round 1
// baseline (speedup 1.0000x reference)
#include <cuda_runtime.h>
#include <math.h>

// B=8, S=1024, E=512, H=16, D=32
#define NB 8
#define NS 1024
#define NE 512
#define NH 16
#define ND 32

// scratch: q,k,v in [B,H,S,D] layout (16 MB each)
__device__ float g_q[NB*NH*NS*ND];
__device__ float g_k[NB*NH*NS*ND];
__device__ float g_v[NB*NH*NS*ND];

// ---------------------------------------------------------------------------
// Projection GEMM: Y[b,h,l,d] = sum_k X[b*S+l, k] * W[h*D+d, k]
// M=8192, N=512, K=512. Block tile 64x64, K-chunk 32, 256 threads, 4x4 micro.
// ---------------------------------------------------------------------------
#define ASTR 68

__global__ __launch_bounds__(256) void proj_kernel(
    const float* __restrict__ X,
    const float* __restrict__ Wq,
    const float* __restrict__ Wk,
    const float* __restrict__ Wv)
{
    __shared__ float As[32*ASTR];  // [k][m]
    __shared__ float Bs[32*ASTR];  // [k][n]
    const float* W = (blockIdx.z == 0) ? Wq : (blockIdx.z == 1) ? Wk : Wv;
    float* Y       = (blockIdx.z == 0) ? g_q : (blockIdx.z == 1) ? g_k : g_v;

    const int tid = threadIdx.x;
    const int tx = tid & 15, ty = tid >> 4;
    const int m0 = blockIdx.y << 6;
    const int n0 = blockIdx.x << 6;

    float acc[4][4] = {};

    for (int kt = 0; kt < NE; kt += 32) {
        __syncthreads();
        #pragma unroll
        for (int t = 0; t < 2; t++) {
            int fi  = tid + (t << 8);      // 0..511
            int row = fi >> 3;             // 0..63
            int kq  = (fi & 7) << 2;       // 0,4,..,28
            float4 av = *(const float4*)(X + (size_t)(m0 + row) * NE + kt + kq);
            As[(kq+0)*ASTR + row] = av.x;
            As[(kq+1)*ASTR + row] = av.y;
            As[(kq+2)*ASTR + row] = av.z;
            As[(kq+3)*ASTR + row] = av.w;
            float4 bv = *(const float4*)(W + (size_t)(n0 + row) * NE + kt + kq);
            Bs[(kq+0)*ASTR + row] = bv.x;
            Bs[(kq+1)*ASTR + row] = bv.y;
            Bs[(kq+2)*ASTR + row] = bv.z;
            Bs[(kq+3)*ASTR + row] = bv.w;
        }
        __syncthreads();
        #pragma unroll
        for (int kk = 0; kk < 32; kk++) {
            float4 av = *(const float4*)(As + kk*ASTR + (ty << 2));
            float4 bv = *(const float4*)(Bs + kk*ASTR + (tx << 2));
            float a[4] = {av.x, av.y, av.z, av.w};
            float b[4] = {bv.x, bv.y, bv.z, bv.w};
            #pragma unroll
            for (int ii = 0; ii < 4; ii++)
                #pragma unroll
                for (int jj = 0; jj < 4; jj++)
                    acc[ii][jj] += a[ii] * b[jj];
        }
    }

    const int n = n0 + (tx << 2);
    const int h = n >> 5, d = n & 31;
    #pragma unroll
    for (int ii = 0; ii < 4; ii++) {
        int m = m0 + (ty << 2) + ii;
        int b = m >> 10, l = m & 1023;
        float4 o = make_float4(acc[ii][0], acc[ii][1], acc[ii][2], acc[ii][3]);
        *(float4*)(Y + ((((size_t)b*NH + h)*NS + l)*ND + d)) = o;
    }
}

// ---------------------------------------------------------------------------
// Fused attention. CTA = (i-block of 64 rows, bh). 256 threads (16x16).
// S[i,j] = (q_i.k_j + q_i.Er[j-i+1023]) / sqrt(D); online softmax; O = P @ V.
// Rel term via per-j-block windowed QE[64 x 127] tile GEMM (window length
// TI+TJ-1 = 127, always in-range since idx = 1023 + (j-i) in [0,2046]).
// ---------------------------------------------------------------------------
#define QK_STR 68
#define E_STR  132
#define P_STR  68
// smem floats: Q 2176 | K 2176 | E 4224 | V 2048 | QE/P union 8192 = 18816
#define SMEM_FLOATS 18816

__global__ __launch_bounds__(256) void attn_kernel(
    const float* __restrict__ Er, float* __restrict__ out)
{
    extern __shared__ float sm[];
    float* Qs  = sm;             // [32][68]  transposed: [d][i]
    float* Ks  = sm + 2176;      // [32][68]  transposed: [d][j]
    float* Es  = sm + 4352;      // [32][132] transposed: [d][w], w in 0..127
    float* Vs  = sm + 8576;      // [64][32]  natural:    [j][d]
    float* QEs = sm + 10624;     // [64][128] QE tile; reused as Ps[64][68]

    const int tid = threadIdx.x;
    const int tx = tid & 15, ty = tid >> 4;
    const int bh = blockIdx.y;
    const int i0 = blockIdx.x << 6;
    const float* qptr = g_q + (size_t)bh * NS * ND;
    const float* kptr = g_k + (size_t)bh * NS * ND;
    const float* vptr = g_v + (size_t)bh * NS * ND;

    // load Q tile transposed
    #pragma unroll
    for (int t = 0; t < 2; t++) {
        int fi  = tid + (t << 8);
        int row = fi >> 3;
        int kq  = (fi & 7) << 2;
        float4 qv = *(const float4*)(qptr + (size_t)(i0 + row) * ND + kq);
        Qs[(kq+0)*QK_STR + row] = qv.x;
        Qs[(kq+1)*QK_STR + row] = qv.y;
        Qs[(kq+2)*QK_STR + row] = qv.z;
        Qs[(kq+3)*QK_STR + row] = qv.w;
    }

    float m_run[4], l_run[4], O[4][2];
    #pragma unroll
    for (int ii = 0; ii < 4; ii++) {
        m_run[ii] = -3.0e38f; l_run[ii] = 0.f; O[ii][0] = 0.f; O[ii][1] = 0.f;
    }
    const float sc = 0.17677669529663687f;  // 1/sqrt(32)

    for (int j0 = 0; j0 < NS; j0 += 64) {
        __syncthreads();  // prior P@V / QE reads complete before overwrite

        // load K (transposed) + V (natural)
        #pragma unroll
        for (int t = 0; t < 2; t++) {
            int fi  = tid + (t << 8);
            int row = fi >> 3;
            int kq  = (fi & 7) << 2;
            float4 kv = *(const float4*)(kptr + (size_t)(j0 + row) * ND + kq);
            Ks[(kq+0)*QK_STR + row] = kv.x;
            Ks[(kq+1)*QK_STR + row] = kv.y;
            Ks[(kq+2)*QK_STR + row] = kv.z;
            Ks[(kq+3)*QK_STR + row] = kv.w;
            float4 vv = *(const float4*)(vptr + (size_t)(j0 + row) * ND + kq);
            *(float4*)(Vs + row*ND + kq) = vv;
        }
        // load Er window transposed: rows base..base+126, w=127 zero-padded
        const int base = j0 - i0 + 960;  // = j0 - i0 + 1023 - 63, always >= 0
        #pragma unroll
        for (int t = 0; t < 4; t++) {
            int fi = tid + (t << 8);     // 0..1023
            int w  = fi >> 3;            // 0..127
            int kq = (fi & 7) << 2;
            float4 ev = make_float4(0.f, 0.f, 0.f, 0.f);
            if (w < 127)
                ev = *(const float4*)(Er + (size_t)(base + w) * ND + kq);
            Es[(kq+0)*E_STR + w] = ev.x;
            Es[(kq+1)*E_STR + w] = ev.y;
            Es[(kq+2)*E_STR + w] = ev.z;
            Es[(kq+3)*E_STR + w] = ev.w;
        }
        __syncthreads();

        // QE tile GEMM: QEs[i][w] = sum_d q[i,d] * Er_win[w,d]; micro 4x8
        {
            float qe[4][8] = {};
            #pragma unroll
            for (int kk = 0; kk < 32; kk++) {
                float4 av = *(const float4*)(Qs + kk*QK_STR + (ty << 2));
                float4 e0 = *(const float4*)(Es + kk*E_STR + (tx << 3));
                float4 e1 = *(const float4*)(Es + kk*E_STR + (tx << 3) + 4);
                float a[4] = {av.x, av.y, av.z, av.w};
                float e[8] = {e0.x, e0.y, e0.z, e0.w, e1.x, e1.y, e1.z, e1.w};
                #pragma unroll
                for (int ii = 0; ii < 4; ii++)
                    #pragma unroll
                    for (int ww = 0; ww < 8; ww++)
                        qe[ii][ww] += a[ii] * e[ww];
            }
            #pragma unroll
            for (int ii = 0; ii < 4; ii++) {
                float* dst = QEs + (((ty << 2) + ii) << 7) + (tx << 3);
                *(float4*)(dst)     = make_float4(qe[ii][0], qe[ii][1], qe[ii][2], qe[ii][3]);
                *(float4*)(dst + 4) = make_float4(qe[ii][4], qe[ii][5], qe[ii][6], qe[ii][7]);
            }
        }
        __syncthreads();

        // S tile GEMM + rel bias + scale
        float s[4][4] = {};
        #pragma unroll
        for (int kk = 0; kk < 32; kk++) {
            float4 av = *(const float4*)(Qs + kk*QK_STR + (ty << 2));
            float4 bv = *(const float4*)(Ks + kk*QK_STR + (tx << 2));
            float a[4] = {av.x, av.y, av.z, av.w};
            float b[4] = {bv.x, bv.y, bv.z, bv.w};
            #pragma unroll
            for (int ii = 0; ii < 4; ii++)
                #pragma unroll
                for (int jj = 0; jj < 4; jj++)
                    s[ii][jj] += a[ii] * b[jj];
        }
        #pragma unroll
        for (int ii = 0; ii < 4; ii++) {
            int irow = (ty << 2) + ii;
            #pragma unroll
            for (int jj = 0; jj < 4; jj++) {
                int w = (tx << 2) + jj - irow + 63;   // in [0,126]
                s[ii][jj] = (s[ii][jj] + QEs[(irow << 7) + w]) * sc;
            }
        }
        __syncthreads();  // all QE reads done before Ps overwrites the buffer

        // online softmax across the 16 tx lanes (contiguous half-warp)
        #pragma unroll
        for (int ii = 0; ii < 4; ii++) {
            float mx = fmaxf(fmaxf(s[ii][0], s[ii][1]), fmaxf(s[ii][2], s[ii][3]));
            #pragma unroll
            for (int o = 8; o >= 1; o >>= 1)
                mx = fmaxf(mx, __shfl_xor_sync(0xffffffffu, mx, o));
            float mnew  = fmaxf(m_run[ii], mx);
            float alpha = __expf(m_run[ii] - mnew);
            m_run[ii] = mnew;
            float sum = 0.f;
            #pragma unroll
            for (int jj = 0; jj < 4; jj++) {
                float p = __expf(s[ii][jj] - mnew);
                s[ii][jj] = p;
                sum += p;
            }
            #pragma unroll
            for (int o = 8; o >= 1; o >>= 1)
                sum += __shfl_xor_sync(0xffffffffu, sum, o);
            l_run[ii] = l_run[ii] * alpha + sum;
            O[ii][0] *= alpha;
            O[ii][1] *= alpha;
            *(float4*)(QEs + ((ty << 2) + ii)*P_STR + (tx << 2)) =
                make_float4(s[ii][0], s[ii][1], s[ii][2], s[ii][3]);
        }
        __syncthreads();

        // O += P @ V  (O tile [64 x 32], thread: 4 rows x 2 d-cols, j unroll 4)
        #pragma unroll 4
        for (int j4 = 0; j4 < 64; j4 += 4) {
            float pr[4][4];
            #pragma unroll
            for (int ii = 0; ii < 4; ii++) {
                float4 p = *(const float4*)(QEs + ((ty << 2) + ii)*P_STR + j4);
                pr[ii][0] = p.x; pr[ii][1] = p.y; pr[ii][2] = p.z; pr[ii][3] = p.w;
            }
            float vv[4][2];
            #pragma unroll
            for (int jj = 0; jj < 4; jj++) {
                float2 v = *(const float2*)(Vs + (j4 + jj)*ND + (tx << 1));
                vv[jj][0] = v.x; vv[jj][1] = v.y;
            }
            #pragma unroll
            for (int ii = 0; ii < 4; ii++)
                #pragma unroll
                for (int jj = 0; jj < 4; jj++) {
                    O[ii][0] += pr[ii][jj] * vv[jj][0];
                    O[ii][1] += pr[ii][jj] * vv[jj][1];
                }
        }
    }

    // epilogue: divide by l, write to [b, l, h*D + d]
    const int b = bh >> 4, h = bh & 15;
    #pragma unroll
    for (int ii = 0; ii < 4; ii++) {
        float inv = 1.0f / l_run[ii];
        int i = i0 + (ty << 2) + ii;
        size_t off = ((size_t)(b*NS + i))*NE + (h << 5) + (tx << 1);
        *(float2*)(out + off) = make_float2(O[ii][0]*inv, O[ii][1]*inv);
    }
}

// ---------------------------------------------------------------------------
extern "C" void kernel_launch(void* const* d_in, const int* in_sizes, int n_in,
                              void* d_out, int out_size)
{
    const float* x  = (const float*)d_in[0];
    const float* Wq = (const float*)d_in[1];
    const float* Wk = (const float*)d_in[2];
    const float* Wv = (const float*)d_in[3];
    const float* Er = (const float*)d_in[4];
    float* out = (float*)d_out;

    (void)in_sizes; (void)n_in; (void)out_size;

    cudaFuncSetAttribute(attn_kernel,
                         cudaFuncAttributeMaxDynamicSharedMemorySize,
                         SMEM_FLOATS * sizeof(float));

    // q,k,v projections: grid.z selects W / destination
    proj_kernel<<<dim3(NE/64, (NB*NS)/64, 3), 256>>>(x, Wq, Wk, Wv);

    // fused attention: (16 i-blocks, 128 bh)
    attn_kernel<<<dim3(NS/64, NB*NH), 256, SMEM_FLOATS * sizeof(float)>>>(Er, out);
}

// round 2
// speedup vs baseline: 2.6812x; 2.6812x over previous
#include <cuda_runtime.h>
#include <math.h>

// B=8, S=1024, E=512, H=16, D=32
#define NB 8
#define NS 1024
#define NE 512
#define NH 16
#define ND 32

// scratch: q,k,v in [B,H,S,D] layout, values pre-rounded to tf32
__device__ float g_q[NB*NH*NS*ND];
__device__ float g_k[NB*NH*NS*ND];
__device__ float g_v[NB*NH*NS*ND];

// ---------------------------------------------------------------------------
// helpers
// ---------------------------------------------------------------------------
__device__ __forceinline__ unsigned f2tf(float x) {
    unsigned r;
    asm("cvt.rna.tf32.f32 %0, %1;" : "=r"(r) : "f"(x));
    return r;
}

__device__ __forceinline__ void mma_tf32(float c[4], const unsigned a[4],
                                         unsigned b0, unsigned b1) {
    asm volatile(
        "mma.sync.aligned.m16n8k8.row.col.f32.tf32.tf32.f32 "
        "{%0,%1,%2,%3}, {%4,%5,%6,%7}, {%8,%9}, {%0,%1,%2,%3};"
        : "+f"(c[0]), "+f"(c[1]), "+f"(c[2]), "+f"(c[3])
        : "r"(a[0]), "r"(a[1]), "r"(a[2]), "r"(a[3]), "r"(b0), "r"(b1));
}

// ---------------------------------------------------------------------------
// Projection GEMM (tf32 mma): Y[b,h,l,d] = sum_k X[m,k] * W[n,k]
// M=8192, N=512, K=512. CTA: 256 thr, tile 128x128, K-chunk 16.
// Warps 2(m) x 4(n): warp tile 64x32. Output rounded to tf32.
// ---------------------------------------------------------------------------
#define PSTR 20

__global__ __launch_bounds__(256, 1) void proj_kernel(
    const float* __restrict__ X,
    const float* __restrict__ Wq,
    const float* __restrict__ Wk,
    const float* __restrict__ Wv)
{
    __shared__ float Xs[128*PSTR];
    __shared__ float Ws[128*PSTR];
    const float* W = (blockIdx.z == 0) ? Wq : (blockIdx.z == 1) ? Wk : Wv;
    float* Y       = (blockIdx.z == 0) ? g_q : (blockIdx.z == 1) ? g_k : g_v;

    const int tid  = threadIdx.x;
    const int lane = tid & 31;
    const int wid  = tid >> 5;
    const int wm   = (wid >> 2) << 6;   // 0 / 64
    const int wn   = (wid & 3) << 5;    // 0,32,64,96
    const int gr   = lane >> 2;
    const int gc   = lane & 3;
    const int m0   = blockIdx.y << 7;
    const int n0   = blockIdx.x << 7;

    float C[4][4][4] = {};

    // prefetch chunk 0
    float4 xa[2], wa[2];
    #pragma unroll
    for (int t = 0; t < 2; t++) {
        int idx = tid + (t << 8);
        int row = idx >> 2, q = (idx & 3) << 2;
        xa[t] = *(const float4*)(X + (size_t)(m0 + row) * NE + q);
        wa[t] = *(const float4*)(W + (size_t)(n0 + row) * NE + q);
    }

    for (int kt = 0; kt < NE; kt += 16) {
        // store prefetched chunk into smem (tf32-rounded)
        #pragma unroll
        for (int t = 0; t < 2; t++) {
            int idx = tid + (t << 8);
            int row = idx >> 2, q = (idx & 3) << 2;
            float* xd = Xs + row*PSTR + q;
            xd[0] = __uint_as_float(f2tf(xa[t].x));
            xd[1] = __uint_as_float(f2tf(xa[t].y));
            xd[2] = __uint_as_float(f2tf(xa[t].z));
            xd[3] = __uint_as_float(f2tf(xa[t].w));
            float* wd = Ws + row*PSTR + q;
            wd[0] = __uint_as_float(f2tf(wa[t].x));
            wd[1] = __uint_as_float(f2tf(wa[t].y));
            wd[2] = __uint_as_float(f2tf(wa[t].z));
            wd[3] = __uint_as_float(f2tf(wa[t].w));
        }
        __syncthreads();

        // prefetch next chunk
        if (kt + 16 < NE) {
            #pragma unroll
            for (int t = 0; t < 2; t++) {
                int idx = tid + (t << 8);
                int row = idx >> 2, q = (idx & 3) << 2;
                xa[t] = *(const float4*)(X + (size_t)(m0 + row) * NE + kt + 16 + q);
                wa[t] = *(const float4*)(W + (size_t)(n0 + row) * NE + kt + 16 + q);
            }
        }

        // fragments + mma
        unsigned aF[4][2][4], bF[4][2][2];
        #pragma unroll
        for (int mt = 0; mt < 4; mt++)
            #pragma unroll
            for (int ks = 0; ks < 2; ks++) {
                int r = wm + (mt << 4) + gr, k0 = ks << 3;
                aF[mt][ks][0] = __float_as_uint(Xs[r*PSTR + k0 + gc]);
                aF[mt][ks][1] = __float_as_uint(Xs[(r+8)*PSTR + k0 + gc]);
                aF[mt][ks][2] = __float_as_uint(Xs[r*PSTR + k0 + 4 + gc]);
                aF[mt][ks][3] = __float_as_uint(Xs[(r+8)*PSTR + k0 + 4 + gc]);
            }
        #pragma unroll
        for (int nt = 0; nt < 4; nt++)
            #pragma unroll
            for (int ks = 0; ks < 2; ks++) {
                int n = wn + (nt << 3) + gr, k0 = ks << 3;
                bF[nt][ks][0] = __float_as_uint(Ws[n*PSTR + k0 + gc]);
                bF[nt][ks][1] = __float_as_uint(Ws[n*PSTR + k0 + 4 + gc]);
            }
        #pragma unroll
        for (int mt = 0; mt < 4; mt++)
            #pragma unroll
            for (int nt = 0; nt < 4; nt++) {
                mma_tf32(C[mt][nt], aF[mt][0], bF[nt][0][0], bF[nt][0][1]);
                mma_tf32(C[mt][nt], aF[mt][1], bF[nt][1][0], bF[nt][1][1]);
            }
        __syncthreads();
    }

    // epilogue: round to tf32, write [b,h,l,d]
    #pragma unroll
    for (int mt = 0; mt < 4; mt++) {
        int r = m0 + wm + (mt << 4) + gr;
        #pragma unroll
        for (int nt = 0; nt < 4; nt++) {
            int n = n0 + wn + (nt << 3) + (gc << 1);
            int h = n >> 5, d = n & 31;
            int b0r = r >> 10, l0 = r & 1023;
            float2 v0 = make_float2(__uint_as_float(f2tf(C[mt][nt][0])),
                                    __uint_as_float(f2tf(C[mt][nt][1])));
            *(float2*)(Y + (((size_t)(b0r*NH + h))*NS + l0)*ND + d) = v0;
            int r1 = r + 8;
            int b1r = r1 >> 10, l1 = r1 & 1023;
            float2 v1 = make_float2(__uint_as_float(f2tf(C[mt][nt][2])),
                                    __uint_as_float(f2tf(C[mt][nt][3])));
            *(float2*)(Y + (((size_t)(b1r*NH + h))*NS + l1)*ND + d) = v1;
        }
    }
}

// ---------------------------------------------------------------------------
// Fused attention (tf32 mma). CTA = 128 thr (4 warps), tile 64(i) x 64(j).
// Warp w owns rows [16w, 16w+16). All GEMMs via m16n8k8 tf32.
// Smem: Qs[64][40] | Ks[64][40] | Es[128][40] (Vs overlays) | QEs/Ps[64][136]
// ---------------------------------------------------------------------------
#define SMEM_FLOATS 18944   // 75776 bytes -> 3 CTAs/SM

__global__ __launch_bounds__(128, 3) void attn_kernel(
    const float* __restrict__ Er, float* __restrict__ out)
{
    extern __shared__ float sm[];
    float* Qs  = sm;            // [64][40]
    float* Ks  = sm + 2560;     // [64][40]
    float* Es  = sm + 5120;     // [128][40], rows 0..126 = Er window
    float* Vs  = Es;            // overlay: [64][40]
    float* QEs = sm + 10240;    // [64][136]; Ps overlays
    float* Ps  = QEs;

    const int tid  = threadIdx.x;
    const int lane = tid & 31;
    const int wid  = tid >> 5;
    const int wr   = wid << 4;      // warp row base
    const int gr   = lane >> 2;     // 0..7
    const int gc   = lane & 3;      // 0..3

    const int bh = blockIdx.y;
    const int i0 = blockIdx.x << 6;
    const float* qptr = g_q + (size_t)bh * (NS*ND);
    const float* kptr = g_k + (size_t)bh * (NS*ND);
    const float* vptr = g_v + (size_t)bh * (NS*ND);

    // fill Qs (already tf32-rounded by proj)
    #pragma unroll
    for (int t = 0; t < 4; t++) {
        int idx = tid + (t << 7);
        int i = idx >> 3, q = (idx & 7) << 2;
        *(float4*)(Qs + i*40 + q) = *(const float4*)(qptr + (size_t)(i0 + i)*ND + q);
    }
    __syncthreads();

    // Q A-fragments: persist across all j-blocks
    unsigned aQ[4][4];
    #pragma unroll
    for (int ks = 0; ks < 4; ks++) {
        int k0 = ks << 3;
        aQ[ks][0] = __float_as_uint(Qs[(wr+gr)*40   + k0 + gc]);
        aQ[ks][1] = __float_as_uint(Qs[(wr+gr+8)*40 + k0 + gc]);
        aQ[ks][2] = __float_as_uint(Qs[(wr+gr)*40   + k0 + 4 + gc]);
        aQ[ks][3] = __float_as_uint(Qs[(wr+gr+8)*40 + k0 + 4 + gc]);
    }

    float m_run[2] = {-1e30f, -1e30f};
    float l_run[2] = {0.f, 0.f};
    float O[4][4] = {};
    const float sc = 0.17677669529663687f;  // 1/sqrt(32)

    for (int j0 = 0; j0 < NS; j0 += 64) {
        __syncthreads();  // guard: prev PV reads of Vs/Ps done before refill

        // fill Ks
        #pragma unroll
        for (int t = 0; t < 4; t++) {
            int idx = tid + (t << 7);
            int j = idx >> 3, q = (idx & 7) << 2;
            *(float4*)(Ks + j*40 + q) = *(const float4*)(kptr + (size_t)(j0 + j)*ND + q);
        }
        // fill Es: Er window rows base..base+126, tf32-rounded
        const int base = j0 - i0 + 960;
        #pragma unroll
        for (int t = 0; t < 8; t++) {
            int idx = tid + (t << 7);
            if (idx < 1016) {  // 127*8 float4s
                int w = idx >> 3, q = (idx & 7) << 2;
                float4 e = *(const float4*)(Er + (size_t)(base + w)*ND + q);
                float* d = Es + w*40 + q;
                d[0] = __uint_as_float(f2tf(e.x));
                d[1] = __uint_as_float(f2tf(e.y));
                d[2] = __uint_as_float(f2tf(e.z));
                d[3] = __uint_as_float(f2tf(e.w));
            }
        }
        __syncthreads();

        // QE GEMM: QEs[i][w] = q_i . Er_win[w], 16 n-tiles
        #pragma unroll
        for (int nt = 0; nt < 16; nt++) {
            float c[4] = {0.f, 0.f, 0.f, 0.f};
            int n0 = nt << 3;
            #pragma unroll
            for (int ks = 0; ks < 4; ks++) {
                int k0 = ks << 3;
                unsigned b0 = __float_as_uint(Es[(n0+gr)*40 + k0 + gc]);
                unsigned b1 = __float_as_uint(Es[(n0+gr)*40 + k0 + 4 + gc]);
                mma_tf32(c, aQ[ks], b0, b1);
            }
            *(float2*)(QEs + (wr+gr)*136   + n0 + (gc << 1)) = make_float2(c[0], c[1]);
            *(float2*)(QEs + (wr+gr+8)*136 + n0 + (gc << 1)) = make_float2(c[2], c[3]);
        }
        __syncthreads();  // all Es fragment reads complete

        // fill Vs (overlays Es)
        #pragma unroll
        for (int t = 0; t < 4; t++) {
            int idx = tid + (t << 7);
            int j = idx >> 3, q = (idx & 7) << 2;
            *(float4*)(Vs + j*40 + q) = *(const float4*)(vptr + (size_t)(j0 + j)*ND + q);
        }

        // QK GEMM: 8 n-tiles
        float s[8][4];
        #pragma unroll
        for (int nt = 0; nt < 8; nt++) {
            s[nt][0] = s[nt][1] = s[nt][2] = s[nt][3] = 0.f;
            int n0 = nt << 3;
            #pragma unroll
            for (int ks = 0; ks < 4; ks++) {
                int k0 = ks << 3;
                unsigned b0 = __float_as_uint(Ks[(n0+gr)*40 + k0 + gc]);
                unsigned b1 = __float_as_uint(Ks[(n0+gr)*40 + k0 + 4 + gc]);
                mma_tf32(s[nt], aQ[ks], b0, b1);
            }
        }
        // add rel-pos bias (gather from QEs) + scale
        {
            int r0 = wr + gr, r1 = r0 + 8;
            #pragma unroll
            for (int nt = 0; nt < 8; nt++) {
                int jl = (nt << 3) + (gc << 1);
                s[nt][0] = (s[nt][0] + QEs[r0*136 + jl     - r0 + 63]) * sc;
                s[nt][1] = (s[nt][1] + QEs[r0*136 + jl + 1 - r0 + 63]) * sc;
                s[nt][2] = (s[nt][2] + QEs[r1*136 + jl     - r1 + 63]) * sc;
                s[nt][3] = (s[nt][3] + QEs[r1*136 + jl + 1 - r1 + 63]) * sc;
            }
        }

        // online softmax (rows r0, r1; 4 lanes per row -> shfl over lanes 1,2)
        float mx0 = -1e30f, mx1 = -1e30f;
        #pragma unroll
        for (int nt = 0; nt < 8; nt++) {
            mx0 = fmaxf(mx0, fmaxf(s[nt][0], s[nt][1]));
            mx1 = fmaxf(mx1, fmaxf(s[nt][2], s[nt][3]));
        }
        mx0 = fmaxf(mx0, __shfl_xor_sync(0xffffffffu, mx0, 1));
        mx0 = fmaxf(mx0, __shfl_xor_sync(0xffffffffu, mx0, 2));
        mx1 = fmaxf(mx1, __shfl_xor_sync(0xffffffffu, mx1, 1));
        mx1 = fmaxf(mx1, __shfl_xor_sync(0xffffffffu, mx1, 2));
        float mn0 = fmaxf(m_run[0], mx0), mn1 = fmaxf(m_run[1], mx1);
        float al0 = __expf(m_run[0] - mn0), al1 = __expf(m_run[1] - mn1);
        m_run[0] = mn0; m_run[1] = mn1;

        float sum0 = 0.f, sum1 = 0.f;
        #pragma unroll
        for (int nt = 0; nt < 8; nt++) {
            s[nt][0] = __expf(s[nt][0] - mn0); sum0 += s[nt][0];
            s[nt][1] = __expf(s[nt][1] - mn0); sum0 += s[nt][1];
            s[nt][2] = __expf(s[nt][2] - mn1); sum1 += s[nt][2];
            s[nt][3] = __expf(s[nt][3] - mn1); sum1 += s[nt][3];
        }
        sum0 += __shfl_xor_sync(0xffffffffu, sum0, 1);
        sum0 += __shfl_xor_sync(0xffffffffu, sum0, 2);
        sum1 += __shfl_xor_sync(0xffffffffu, sum1, 1);
        sum1 += __shfl_xor_sync(0xffffffffu, sum1, 2);
        l_run[0] = l_run[0]*al0 + sum0;
        l_run[1] = l_run[1]*al1 + sum1;
        #pragma unroll
        for (int ntd = 0; ntd < 4; ntd++) {
            O[ntd][0] *= al0; O[ntd][1] *= al0;
            O[ntd][2] *= al1; O[ntd][3] *= al1;
        }

        // store P (tf32) into Ps (overlays QEs; own-warp rows only)
        {
            int r0 = wr + gr, r1 = r0 + 8;
            #pragma unroll
            for (int nt = 0; nt < 8; nt++) {
                int n0 = nt << 3;
                uint2 p0 = make_uint2(f2tf(s[nt][0]), f2tf(s[nt][1]));
                uint2 p1 = make_uint2(f2tf(s[nt][2]), f2tf(s[nt][3]));
                *(uint2*)(Ps + r0*136 + n0 + (gc << 1)) = p0;
                *(uint2*)(Ps + r1*136 + n0 + (gc << 1)) = p1;
            }
        }
        __syncthreads();  // Vs filled by all threads

        // O += P @ V : 8 k-steps x 4 d-tiles
        #pragma unroll
        for (int ks = 0; ks < 8; ks++) {
            int k0 = ks << 3;
            unsigned a[4];
            a[0] = __float_as_uint(Ps[(wr+gr)*136   + k0 + gc]);
            a[1] = __float_as_uint(Ps[(wr+gr+8)*136 + k0 + gc]);
            a[2] = __float_as_uint(Ps[(wr+gr)*136   + k0 + 4 + gc]);
            a[3] = __float_as_uint(Ps[(wr+gr+8)*136 + k0 + 4 + gc]);
            #pragma unroll
            for (int ntd = 0; ntd < 4; ntd++) {
                int n0 = ntd << 3;
                unsigned b0 = __float_as_uint(Vs[(k0+gc)*40   + n0 + gr]);
                unsigned b1 = __float_as_uint(Vs[(k0+4+gc)*40 + n0 + gr]);
                mma_tf32(O[ntd], a, b0, b1);
            }
        }
    }

    // epilogue: normalize, write out[b, i, h*32+d]
    const int b = bh >> 4, hh = bh & 15;
    const float inv0 = 1.0f / l_run[0];
    const float inv1 = 1.0f / l_run[1];
    const int r0 = i0 + wr + gr, r1 = r0 + 8;
    #pragma unroll
    for (int ntd = 0; ntd < 4; ntd++) {
        int d = (ntd << 3) + (gc << 1);
        *(float2*)(out + ((size_t)(b*NS + r0))*NE + (hh << 5) + d) =
            make_float2(O[ntd][0]*inv0, O[ntd][1]*inv0);
        *(float2*)(out + ((size_t)(b*NS + r1))*NE + (hh << 5) + d) =
            make_float2(O[ntd][2]*inv1, O[ntd][3]*inv1);
    }
}

// ---------------------------------------------------------------------------
extern "C" void kernel_launch(void* const* d_in, const int* in_sizes, int n_in,
                              void* d_out, int out_size)
{
    const float* x  = (const float*)d_in[0];
    const float* Wq = (const float*)d_in[1];
    const float* Wk = (const float*)d_in[2];
    const float* Wv = (const float*)d_in[3];
    const float* Er = (const float*)d_in[4];
    float* out = (float*)d_out;
    (void)in_sizes; (void)n_in; (void)out_size;

    cudaFuncSetAttribute(attn_kernel,
                         cudaFuncAttributeMaxDynamicSharedMemorySize,
                         SMEM_FLOATS * sizeof(float));

    proj_kernel<<<dim3(4, 64, 3), 256>>>(x, Wq, Wk, Wv);
    attn_kernel<<<dim3(NS/64, NB*NH), 128, SMEM_FLOATS * sizeof(float)>>>(Er, out);
}